// round 1
// baseline (speedup 1.0000x reference)
#include <cuda_runtime.h>
#include <cstdint>

// Problem shape (fixed by the dataset): x[B=4,S=4096,H=1024], conv_w[L=20,H,H], norm_w[H]
#define H_DIM   1024
#define L_DIM   20
#define M_TOTAL 16384   // B*S
#define K_DIM   1024
#define N_DIM   1024
#define EPS     1e-6f

// Scratch: averaged weight matrix W[o][i] (tf32-rounded), 4 MB — fits in L2.
__device__ float g_W[H_DIM * H_DIM];

__device__ __forceinline__ uint32_t f2tf32(float f) {
    uint32_t r;
    asm("cvt.rna.tf32.f32 %0, %1;" : "=r"(r) : "f"(f));
    return r;
}

// ---------------------------------------------------------------------------
// Kernel 1: W[o,i] = (1/L) * sum_l conv_w[l,o,i], rounded to tf32.
// 80 MB read, 4 MB write. Memory-bound (~12 us floor).
// ---------------------------------------------------------------------------
__global__ void reduce_w_kernel(const float* __restrict__ conv_w) {
    int idx = (blockIdx.x * blockDim.x + threadIdx.x) * 4;
    const float inv = 1.0f / (float)L_DIM;
    float4 acc = make_float4(0.f, 0.f, 0.f, 0.f);
#pragma unroll
    for (int l = 0; l < L_DIM; l++) {
        float4 v = *(const float4*)(conv_w + (size_t)l * H_DIM * H_DIM + idx);
        acc.x += v.x; acc.y += v.y; acc.z += v.z; acc.w += v.w;
    }
    float4 o;
    o.x = __uint_as_float(f2tf32(acc.x * inv));
    o.y = __uint_as_float(f2tf32(acc.y * inv));
    o.z = __uint_as_float(f2tf32(acc.z * inv));
    o.w = __uint_as_float(f2tf32(acc.w * inv));
    *(float4*)(g_W + idx) = o;
}

// ---------------------------------------------------------------------------
// Kernel 2: y[m,n] = sum_k x[m,k] * W[n,k]   (TF32 tensor cores, fp32 accum)
// CTA tile 128x128, K-tile 32. 8 warps in a 4(m) x 2(n) grid; each warp owns
// a 32x64 tile = 2x8 m16n8k8 fragments.
// Smem row stride 36 floats: fragment loads hit 32 distinct banks
// (bank = (4*group + k) mod 32), and 16B-aligned float4 stores remain aligned.
// ---------------------------------------------------------------------------
__global__ __launch_bounds__(256)
void gemm_tf32_kernel(const float* __restrict__ x, float* __restrict__ y) {
    __shared__ float As[128][36];
    __shared__ float Bs[128][36];

    const int tid  = threadIdx.x;
    const int warp = tid >> 5;
    const int lane = tid & 31;
    const int wm   = warp & 3;   // warp row (m)
    const int wn   = warp >> 2;  // warp col (n)
    const int g    = lane >> 2;  // groupID 0..7
    const int tg   = lane & 3;   // thread-in-group 0..3

    const int bm = blockIdx.y * 128;
    const int bn = blockIdx.x * 128;

    float acc[2][8][4];
#pragma unroll
    for (int mi = 0; mi < 2; mi++)
#pragma unroll
        for (int ni = 0; ni < 8; ni++)
#pragma unroll
            for (int c = 0; c < 4; c++) acc[mi][ni][c] = 0.f;

    const int lrow = tid >> 3;        // 0..31
    const int lcol = (tid & 7) * 4;   // 0..28

    for (int kt = 0; kt < K_DIM; kt += 32) {
#pragma unroll
        for (int r = 0; r < 128; r += 32) {
            float4 va = *(const float4*)(x   + (size_t)(bm + lrow + r) * K_DIM + kt + lcol);
            float4 vb = *(const float4*)(g_W + (size_t)(bn + lrow + r) * K_DIM + kt + lcol);
            // round x to tf32 (W is pre-rounded in kernel 1)
            va.x = __uint_as_float(f2tf32(va.x));
            va.y = __uint_as_float(f2tf32(va.y));
            va.z = __uint_as_float(f2tf32(va.z));
            va.w = __uint_as_float(f2tf32(va.w));
            *(float4*)&As[lrow + r][lcol] = va;
            *(float4*)&Bs[lrow + r][lcol] = vb;
        }
        __syncthreads();

#pragma unroll
        for (int kk = 0; kk < 32; kk += 8) {
            uint32_t a[2][4];
#pragma unroll
            for (int mi = 0; mi < 2; mi++) {
                const int mr = wm * 32 + mi * 16;
                a[mi][0] = __float_as_uint(As[mr + g    ][kk + tg    ]);
                a[mi][1] = __float_as_uint(As[mr + g + 8][kk + tg    ]);
                a[mi][2] = __float_as_uint(As[mr + g    ][kk + tg + 4]);
                a[mi][3] = __float_as_uint(As[mr + g + 8][kk + tg + 4]);
            }
            uint32_t b[8][2];
#pragma unroll
            for (int ni = 0; ni < 8; ni++) {
                const int nc = wn * 64 + ni * 8;
                b[ni][0] = __float_as_uint(Bs[nc + g][kk + tg    ]);
                b[ni][1] = __float_as_uint(Bs[nc + g][kk + tg + 4]);
            }
#pragma unroll
            for (int mi = 0; mi < 2; mi++)
#pragma unroll
                for (int ni = 0; ni < 8; ni++)
                    asm volatile(
                        "mma.sync.aligned.m16n8k8.row.col.f32.tf32.tf32.f32 "
                        "{%0,%1,%2,%3}, {%4,%5,%6,%7}, {%8,%9}, {%0,%1,%2,%3};"
                        : "+f"(acc[mi][ni][0]), "+f"(acc[mi][ni][1]),
                          "+f"(acc[mi][ni][2]), "+f"(acc[mi][ni][3])
                        : "r"(a[mi][0]), "r"(a[mi][1]), "r"(a[mi][2]), "r"(a[mi][3]),
                          "r"(b[ni][0]), "r"(b[ni][1]));
        }
        __syncthreads();
    }

    // Epilogue: c0/c1 at (g, 2*tg), c2/c3 at (g+8, 2*tg)
#pragma unroll
    for (int mi = 0; mi < 2; mi++) {
#pragma unroll
        for (int ni = 0; ni < 8; ni++) {
            const int row = bm + wm * 32 + mi * 16 + g;
            const int col = bn + wn * 64 + ni * 8 + tg * 2;
            *(float2*)(y + (size_t)row       * N_DIM + col) =
                make_float2(acc[mi][ni][0], acc[mi][ni][1]);
            *(float2*)(y + (size_t)(row + 8) * N_DIM + col) =
                make_float2(acc[mi][ni][2], acc[mi][ni][3]);
        }
    }
}

// ---------------------------------------------------------------------------
// Kernel 3: in-place RMSNorm over rows of 1024, times norm_w.
// One CTA of 256 threads per row; 1 float4 per thread.
// ---------------------------------------------------------------------------
__global__ void rmsnorm_kernel(float* __restrict__ y, const float* __restrict__ nw) {
    __shared__ float red[8];
    const int row = blockIdx.x;
    const int tid = threadIdx.x;
    float4* p = (float4*)(y + (size_t)row * H_DIM);

    float4 v = p[tid];
    float ss = v.x * v.x + v.y * v.y + v.z * v.z + v.w * v.w;
#pragma unroll
    for (int o = 16; o; o >>= 1) ss += __shfl_xor_sync(0xFFFFFFFFu, ss, o);
    if ((tid & 31) == 0) red[tid >> 5] = ss;
    __syncthreads();
    if (tid < 32) {
        float s = (tid < 8) ? red[tid] : 0.f;
#pragma unroll
        for (int o = 4; o; o >>= 1) s += __shfl_xor_sync(0xFFFFFFFFu, s, o);
        if (tid == 0) red[0] = s;
    }
    __syncthreads();

    const float scale = rsqrtf(red[0] * (1.0f / H_DIM) + EPS);
    float4 w = ((const float4*)nw)[tid];
    v.x *= scale * w.x;
    v.y *= scale * w.y;
    v.z *= scale * w.z;
    v.w *= scale * w.w;
    p[tid] = v;
}

// ---------------------------------------------------------------------------
extern "C" void kernel_launch(void* const* d_in, const int* in_sizes, int n_in,
                              void* d_out, int out_size) {
    const float* x      = (const float*)d_in[0];
    const float* conv_w = (const float*)d_in[1];
    const float* norm_w = (const float*)d_in[2];
    float* out = (float*)d_out;

    // K1: average conv_w over L -> g_W (tf32-rounded)
    reduce_w_kernel<<<(H_DIM * H_DIM) / (256 * 4), 256>>>(conv_w);

    // K2: y = x @ W^T
    dim3 grid(N_DIM / 128, M_TOTAL / 128);
    gemm_tf32_kernel<<<grid, 256>>>(x, out);

    // K3: RMSNorm in-place
    rmsnorm_kernel<<<M_TOTAL, 256>>>(out, norm_w);
}